// round 15
// baseline (speedup 1.0000x reference)
#include <cuda_runtime.h>
#include <math.h>
#include <stdint.h>

typedef unsigned long long ull;

namespace {
constexpr int B = 16, T = 100, N = 128, D = 3;
constexpr int FRAMES = B * T;                 // 1600
constexpr int NIT = 4;                        // frames per pen block
constexpr int PEN_BLOCKS = FRAMES / NIT;      // 400
constexpr int AUX_BLOCKS = 32;                // 50 frames each
constexpr int BLOCKS = PEN_BLOCKS + AUX_BLOCKS;  // 432
constexpr int THREADS = 512;
constexpr int FD = N * D;                     // 384 floats per frame
constexpr int F4 = FD / 4;                    // 96 float4 per frame
constexpr float MIN_DIST = 0.05f;
constexpr float R2 = MIN_DIST * MIN_DIST;     // 0.0025
constexpr float R2_GUARD = R2 + 1e-4f;        // slack for expansion error
}

__device__ float g_pen[PEN_BLOCKS];
__device__ float g_work[AUX_BLOCKS];
__device__ float g_stab[AUX_BLOCKS];
__device__ float g_ke0[AUX_BLOCKS];
__device__ float g_ke1[AUX_BLOCKS];
__device__ unsigned int g_count;              // zero-init; self-resetting

// 80 half-jobs: job -> (frame fl, tile row I, tile col J, col-half ch)
#define TILE_I0 0,0,0,0,0,0,0,0,1,1,1,1,1,1,2,2,2,2,3,3
#define TILE_J0 0,0,1,1,2,2,3,3,1,1,2,2,3,3,2,2,3,3,3,3
#define TILE_C0 0,1,0,1,0,1,0,1,0,1,0,1,0,1,0,1,0,1,0,1
__constant__ unsigned char c_fl[80] = {
    0,0,0,0,0,0,0,0,0,0,0,0,0,0,0,0,0,0,0,0,
    1,1,1,1,1,1,1,1,1,1,1,1,1,1,1,1,1,1,1,1,
    2,2,2,2,2,2,2,2,2,2,2,2,2,2,2,2,2,2,2,2,
    3,3,3,3,3,3,3,3,3,3,3,3,3,3,3,3,3,3,3,3};
__constant__ unsigned char c_I[80] = {TILE_I0, TILE_I0, TILE_I0, TILE_I0};
__constant__ unsigned char c_J[80] = {TILE_J0, TILE_J0, TILE_J0, TILE_J0};
__constant__ unsigned char c_C[80] = {TILE_C0, TILE_C0, TILE_C0, TILE_C0};

// ---- packed f32x2 helpers ----
__device__ __forceinline__ ull pk2(float v) {
    ull r; asm("mov.b64 %0, {%1,%1};" : "=l"(r) : "f"(v)); return r;
}
__device__ __forceinline__ void upk(ull v, uint32_t& lo, uint32_t& hi) {
    asm("mov.b64 {%0,%1}, %2;" : "=r"(lo), "=r"(hi) : "l"(v));
}
__device__ __forceinline__ ull f2add(ull a, ull b) {
    ull r; asm("add.rn.f32x2 %0, %1, %2;" : "=l"(r) : "l"(a), "l"(b)); return r;
}
__device__ __forceinline__ ull f2fma(ull a, ull b, ull c) {
    ull r; asm("fma.rn.f32x2 %0, %1, %2, %3;" : "=l"(r) : "l"(a), "l"(b), "l"(c)); return r;
}
// volatile LDS.128 with literal immediate offset (no address IADD)
#define LDSPI(p0, p1, base, IMM) \
    asm volatile("ld.shared.v2.u64 {%0,%1}, [%2+" #IMM "];" \
                 : "=l"(p0), "=l"(p1) : "r"(base))

__global__ __launch_bounds__(THREADS, 3) void fused_kernel(
    const float* __restrict__ traj,
    const float* __restrict__ vel,
    const float* __restrict__ frc,
    float* __restrict__ out)
{
    const int tid  = threadIdx.x;
    const int wid  = tid >> 5;
    const int lane = tid & 31;
    const int bid  = blockIdx.x;

    __shared__ __align__(16) float4 sXY[NIT][64];
    __shared__ __align__(16) float4 sZW[NIT][64];
    __shared__ __align__(16) float  sT[NIT * FD];
    __shared__ float sm[16][5];

    float penacc = 0.f, wrkacc = 0.f, stabacc = 0.f, ke0acc = 0.f, ke1acc = 0.f;

    if (bid < PEN_BLOCKS) {
        // ================= PEN BLOCK: pure pairwise penetration ==============
        const int f0 = bid * NIT;

        // phase 1: 384 float4 of traj, one per thread
        if (tid < NIT * F4)
            reinterpret_cast<float4*>(sT)[tid] =
                reinterpret_cast<const float4*>(traj)[f0 * F4 + tid];
        __syncthreads();

        // phase 2: build paired SoA (x-pairs, y-pairs | z-pairs, w-pairs)
        {
            const int fl = tid >> 7, p = tid & 127;
            const float x = sT[fl * FD + 3 * p];
            const float y = sT[fl * FD + 3 * p + 1];
            const float z = sT[fl * FD + 3 * p + 2];
            const float w = x * x + y * y + z * z;
            float* bXY = reinterpret_cast<float*>(sXY[fl]);
            float* bZW = reinterpret_cast<float*>(sZW[fl]);
            const int k2 = p >> 1, hl = p & 1;
            bXY[4 * k2 + hl]     = x;
            bXY[4 * k2 + 2 + hl] = y;
            bZW[4 * k2 + hl]     = z;
            bZW[4 * k2 + 2 + hl] = w;
        }
        __syncthreads();

        // phase 3: 80 half-tile jobs, 5 per warp
        #pragma unroll 1
        for (int jj = 0; jj < 5; ++jj) {
            const int job = wid + 16 * jj;
            const int fl  = c_fl[job];
            const int I   = c_I[job];
            const int J   = c_J[job];
            const int ch  = c_C[job];
            const bool diag = (I == J);

            const float* bXY = reinterpret_cast<const float*>(sXY[fl] + I * 16);
            const float* bZW = reinterpret_cast<const float*>(sZW[fl] + I * 16);
            const int k2s = lane >> 1, hls = lane & 1;
            const float Axv = bXY[4 * k2s + hls];
            const float Ayv = bXY[4 * k2s + 2 + hls];
            const float Azv = bZW[4 * k2s + hls];
            const float Awv = bZW[4 * k2s + 2 + hls];
            const ull axp = pk2(-2.0f * Axv);
            const ull ayp = pk2(-2.0f * Ayv);
            const ull azp = pk2(-2.0f * Azv);
            const ull w0g = pk2(Awv - R2_GUARD);

            const uint32_t caXY =
                (uint32_t)__cvta_generic_to_shared(sXY[fl] + J * 16 + ch * 8);
            const uint32_t caZW =
                (uint32_t)__cvta_generic_to_shared(sZW[fl] + J * 16 + ch * 8);

            uint32_t detu = 0, cnt = 0;
            ull xa0,ya0,za0,wa0, xa1,ya1,za1,wa1;
            ull xb0,yb0,zb0,wb0, xb1,yb1,zb1,wb1;

            #define PAIR2(xp,yp,zp,wp) do {                                  \
                ull s_ = f2add(w0g, (wp));                                   \
                s_ = f2fma(axp, (xp), s_);                                   \
                s_ = f2fma(ayp, (yp), s_);                                   \
                s_ = f2fma(azp, (zp), s_);                                   \
                uint32_t lo_, hi_; upk(s_, lo_, hi_);                        \
                if (diag) cnt += (lo_ >> 31) + (hi_ >> 31);                  \
                else      detu |= lo_ | hi_;                                 \
            } while (0)

            LDSPI(xa0,ya0, caXY, 0);   LDSPI(za0,wa0, caZW, 0);
            LDSPI(xa1,ya1, caXY, 16);  LDSPI(za1,wa1, caZW, 16);
            LDSPI(xb0,yb0, caXY, 32);  LDSPI(zb0,wb0, caZW, 32);
            LDSPI(xb1,yb1, caXY, 48);  LDSPI(zb1,wb1, caZW, 48);
            PAIR2(xa0,ya0,za0,wa0);    PAIR2(xa1,ya1,za1,wa1);
            LDSPI(xa0,ya0, caXY, 64);  LDSPI(za0,wa0, caZW, 64);
            LDSPI(xa1,ya1, caXY, 80);  LDSPI(za1,wa1, caZW, 80);
            PAIR2(xb0,yb0,zb0,wb0);    PAIR2(xb1,yb1,zb1,wb1);
            LDSPI(xb0,yb0, caXY, 96);  LDSPI(zb0,wb0, caZW, 96);
            LDSPI(xb1,yb1, caXY, 112); LDSPI(zb1,wb1, caZW, 112);
            PAIR2(xa0,ya0,za0,wa0);    PAIR2(xa1,ya1,za1,wa1);
            PAIR2(xb0,yb0,zb0,wb0);    PAIR2(xb1,yb1,zb1,wb1);
            #undef PAIR2

            const bool selfin = diag && ((lane >> 4) == ch);
            const bool trigger = diag ? (cnt > (selfin ? 1u : 0u))
                                      : ((detu >> 31) != 0u);

            if (trigger) {            // rare exact slow path
                const float* cXY = reinterpret_cast<const float*>(sXY[fl] + J * 16);
                const float* cZW = reinterpret_cast<const float*>(sZW[fl] + J * 16);
                for (int c = 0; c < 16; ++c) {
                    const int k = ch * 16 + c;
                    if (diag && k <= lane) continue;
                    const int ck = k >> 1, chh = k & 1;
                    const float qx = cXY[4 * ck + chh];
                    const float qy = cXY[4 * ck + 2 + chh];
                    const float qz = cZW[4 * ck + chh];
                    float dx = Axv - qx, dy = Ayv - qy, dz = Azv - qz;
                    float e2 = dx * dx + dy * dy + dz * dz;
                    if (e2 < R2) penacc += MIN_DIST - sqrtf(e2);
                }
            }
        }
    } else {
        // ================= AUX BLOCK: streaming side terms ====================
        const int a = bid - PEN_BLOCKS;        // 0..31, 50 frames each
        const size_t base = (size_t)a * 50;    // chunk-aligned within a traj

        // work term: one element per thread, streamed over the chunk's frames
        if (tid < FD) {
            const float* tb = traj + base * FD + tid;
            const float* fb = frc  + base * FD + tid;
            #pragma unroll 7
            for (int fl = 0; fl < 49; ++fl)
                wrkacc += fb[fl * FD] * (tb[(fl + 1) * FD] - tb[fl * FD]);
            if (!(a & 1))                      // even chunk: t=49 < 99 valid
                wrkacc += fb[49 * FD] * (tb[50 * FD] - tb[49 * FD]);
        }

        // boundary vel terms
        if (a & 1) {                           // t = 50..99 chunk
            {   // frames t = 95..98: fr = tid>>7, p = tid&127
                const int fr = tid >> 7, p = tid & 127;
                const float* pv = vel + (base + 45 + fr) * FD + 3 * p;
                float vx = pv[0], vy = pv[1], vz = pv[2];
                stabacc = sqrtf(vx * vx + vy * vy + vz * vz);
            }
            if (tid < 128) {                   // frame t = 99
                const float* pv = vel + (base + 49) * FD + 3 * tid;
                float vx = pv[0], vy = pv[1], vz = pv[2];
                float v2 = vx * vx + vy * vy + vz * vz;
                stabacc += sqrtf(v2);
                ke1acc = 0.5f * v2;
            }
        } else {
            if (tid < 128) {                   // frame t = 0
                const float* pv = vel + base * FD + 3 * tid;
                float vx = pv[0], vy = pv[1], vz = pv[2];
                ke0acc = 0.5f * (vx * vx + vy * vy + vz * vz);
            }
        }
        __syncthreads();                       // keep barrier count uniform? (own block only)
    }

    // ========== block reduction of 5 accumulators ==========
    #pragma unroll
    for (int off = 16; off > 0; off >>= 1) {
        penacc  += __shfl_down_sync(0xffffffffu, penacc,  off);
        wrkacc  += __shfl_down_sync(0xffffffffu, wrkacc,  off);
        stabacc += __shfl_down_sync(0xffffffffu, stabacc, off);
        ke0acc  += __shfl_down_sync(0xffffffffu, ke0acc,  off);
        ke1acc  += __shfl_down_sync(0xffffffffu, ke1acc,  off);
    }
    if (lane == 0) {
        sm[wid][0] = penacc; sm[wid][1] = wrkacc; sm[wid][2] = stabacc;
        sm[wid][3] = ke0acc; sm[wid][4] = ke1acc;
    }
    __syncthreads();
    if (tid == 0) {
        float sp = 0.f, sw = 0.f, ss = 0.f, s0v = 0.f, s1v = 0.f;
        #pragma unroll
        for (int w = 0; w < 16; ++w) {
            sp += sm[w][0]; sw += sm[w][1]; ss += sm[w][2];
            s0v += sm[w][3]; s1v += sm[w][4];
        }
        if (bid < PEN_BLOCKS) {
            g_pen[bid] = sp;
        } else {
            const int a = bid - PEN_BLOCKS;
            g_work[a] = sw; g_stab[a] = ss; g_ke0[a] = s0v; g_ke1[a] = s1v;
        }
    }

    // ========== last block: deterministic final reduction ==========
    __threadfence();
    __shared__ int is_last;
    if (tid == 0) {
        unsigned int old = atomicAdd(&g_count, 1u);
        is_last = (old == BLOCKS - 1) ? 1 : 0;
    }
    __syncthreads();
    if (!is_last) return;

    float pen_s = (tid < PEN_BLOCKS) ? g_pen[tid] : 0.f;
    float wrk_s = 0.f, stab_s = 0.f, k0 = 0.f, k1 = 0.f;
    if (tid < AUX_BLOCKS) {
        wrk_s  = g_work[tid];
        stab_s = g_stab[tid];
        k0     = g_ke0[tid];
        k1     = g_ke1[tid];
    }
    #pragma unroll
    for (int off = 16; off > 0; off >>= 1) {
        pen_s  += __shfl_down_sync(0xffffffffu, pen_s,  off);
        wrk_s  += __shfl_down_sync(0xffffffffu, wrk_s,  off);
        stab_s += __shfl_down_sync(0xffffffffu, stab_s, off);
        k0     += __shfl_down_sync(0xffffffffu, k0,     off);
        k1     += __shfl_down_sync(0xffffffffu, k1,     off);
    }
    if (lane == 0) {
        sm[wid][0] = pen_s; sm[wid][1] = wrk_s; sm[wid][2] = stab_s;
        sm[wid][3] = k0;    sm[wid][4] = k1;
    }
    __syncthreads();
    if (tid == 0) {
        float sp = 0.f, sw = 0.f, ss = 0.f, s0v = 0.f, s1v = 0.f;
        #pragma unroll
        for (int w = 0; w < 16; ++w) {
            sp += sm[w][0]; sw += sm[w][1]; ss += sm[w][2];
            s0v += sm[w][3]; s1v += sm[w][4];
        }
        const float pen_loss  = sp / (float)B / ((float)T * (float)N * (float)(N - 1) * 0.5f);
        const float work_mean = sw / (float)(B * (T - 1) * N);
        const float stab_mean = ss / (float)(B * 5 * N);
        const float ks        = s0v / (float)(B * N);
        const float ke_       = s1v / (float)(B * N);
        out[0] = 10.0f * pen_loss + stab_mean + 0.1f * fabsf(ke_ - ks - work_mean);
        g_count = 0u;   // self-reset for next graph replay
    }
}

extern "C" void kernel_launch(void* const* d_in, const int* in_sizes, int n_in,
                              void* d_out, int out_size)
{
    const float* traj = (const float*)d_in[0];
    const float* vel  = (const float*)d_in[1];
    const float* frc  = (const float*)d_in[2];

    fused_kernel<<<BLOCKS, THREADS>>>(traj, vel, frc, (float*)d_out);
}